// round 9
// baseline (speedup 1.0000x reference)
#include <cuda_runtime.h>
#include <cstdint>

#define N_PAIRS 500000
#define LMAX    4
#define NM      16
#define HID     32
#define NSPEC   4

// Scratch (allocation-free rule: __device__ globals)
__device__ int d_count[NSPEC];
__device__ int d_cursor[NSPEC];
__device__ int d_off[NSPEC + 1];
__device__ int d_sorted[N_PAIRS];

// ---------------- block-local species dtype detection ----------------
// jax randint(int64) silently becomes int32 without x64 mode; detect layout:
// probe odd int32 words 1..511 — genuine int64 (values 0..3) has all-zero
// high words; int32 random 0..3 is nonzero with prob 1-(1/4)^256.
__device__ __forceinline__ int detect_stride(const int* __restrict__ sp32,
                                             int tid, int* shflag) {
    if (tid == 0) *shflag = 0;
    __syncthreads();
    if (tid < 256 && sp32[2 * tid + 1] != 0) atomicOr(shflag, 1);
    __syncthreads();
    return *shflag ? 1 : 2;
}

// ---------------- sort-by-species pipeline ----------------

__global__ void k_hist(const int* __restrict__ sp32) {
    __shared__ int cnt[NSPEC];
    __shared__ int flag;
    int tid = threadIdx.x;
    if (tid < NSPEC) cnt[tid] = 0;
    const int stride = detect_stride(sp32, tid, &flag);
    __syncthreads();
    int i = blockIdx.x * blockDim.x + tid;
    if (i < N_PAIRS) {
        int sp = sp32[i * stride] & 3;
        atomicAdd(&cnt[sp], 1);
    }
    __syncthreads();
    if (tid < NSPEC && cnt[tid] > 0) atomicAdd(&d_count[tid], cnt[tid]);
    // note: d_count zeroed by k_zero below (launched first)
}

__global__ void k_zero() {
    if (threadIdx.x < NSPEC) d_count[threadIdx.x] = 0;
}

__global__ void k_offsets() {
    int acc = 0;
    for (int s = 0; s < NSPEC; ++s) {
        d_off[s] = acc;
        d_cursor[s] = acc;
        acc += d_count[s];
    }
    d_off[NSPEC] = acc;
}

__global__ void k_scatter(const int* __restrict__ sp32) {
    __shared__ int cnt[NSPEC];
    __shared__ int base[NSPEC];
    __shared__ int flag;
    int tid = threadIdx.x;
    if (tid < NSPEC) cnt[tid] = 0;
    const int stride = detect_stride(sp32, tid, &flag);
    __syncthreads();
    int i = blockIdx.x * blockDim.x + tid;
    int sp = 0;
    if (i < N_PAIRS) {
        sp = sp32[i * stride] & 3;
        atomicAdd(&cnt[sp], 1);
    }
    __syncthreads();
    if (tid < NSPEC) {
        base[tid] = (cnt[tid] > 0) ? atomicAdd(&d_cursor[tid], cnt[tid]) : 0;
        cnt[tid] = 0;   // reuse as local rank cursor
    }
    __syncthreads();
    if (i < N_PAIRS) {
        int r = atomicAdd(&cnt[sp], 1);
        d_sorted[base[sp] + r] = i;
    }
}

// ---------------- packed f32x2 helpers ----------------

__device__ __forceinline__ uint64_t pack2(float v) {
    uint64_t r;
    unsigned u = __float_as_uint(v);
    asm("mov.b64 %0, {%1, %1};" : "=l"(r) : "r"(u));
    return r;
}

__device__ __forceinline__ void unpack2(uint64_t p, float& a, float& b) {
    unsigned lo, hi;
    asm("mov.b64 {%0, %1}, %2;" : "=r"(lo), "=r"(hi) : "l"(p));
    a = __uint_as_float(lo);
    b = __uint_as_float(hi);
}

__device__ __forceinline__ void fma2(uint64_t& d, uint64_t a, uint64_t b) {
    asm("fma.rn.f32x2 %0, %1, %2, %0;" : "+l"(d) : "l"(a), "l"(b));
}

__device__ __forceinline__ float silu(float v) {
    return __fdividef(v, 1.0f + __expf(-v));
}

// ---------------- main MLP kernel ----------------

// One fused dense layer using packed f32x2 FMAs (R3-proven codegen).
template <int IN, int OUT, bool ACT>
__device__ __forceinline__ void layer2(const float* __restrict__ w,
                                       const float* __restrict__ in,
                                       float* __restrict__ out) {
    uint64_t acc[OUT / 2];
#pragma unroll
    for (int o = 0; o < OUT / 2; ++o) acc[o] = 0ull;

#pragma unroll
    for (int i = 0; i < IN; ++i) {
        const uint64_t dup = pack2(in[i]);
        const ulonglong2* wrow = reinterpret_cast<const ulonglong2*>(w + i * OUT);
#pragma unroll
        for (int o4 = 0; o4 < OUT / 4; ++o4) {
            ulonglong2 wv = wrow[o4];           // LDS.128 broadcast
            fma2(acc[o4 * 2 + 0], dup, wv.x);
            fma2(acc[o4 * 2 + 1], dup, wv.y);
        }
    }

#pragma unroll
    for (int o2 = 0; o2 < OUT / 2; ++o2) {
        float v0, v1;
        unpack2(acc[o2], v0, v1);
        if (ACT) { v0 = silu(v0); v1 = silu(v1); }
        out[o2 * 2 + 0] = v0;
        out[o2 * 2 + 1] = v1;
    }
}

// Per-l smem weight block for ONE species (3072 floats = 12 KB), 4 l-blocks = 48 KB:
// [0,512) W1 (16x32), [512,1536) W2 (32x32), [1536,2560) W3 (32x32), [2560,3072) W4 (32x16)
#define SPBLK 3072

__global__ void __launch_bounds__(256, 2)    // R3-proven: 128-reg budget, no demotion
k_mlp(const float* __restrict__ xg,
      const float* __restrict__ W1, const float* __restrict__ W2,
      const float* __restrict__ W3, const float* __restrict__ W4,
      float* __restrict__ out) {
    const int s = blockIdx.y;                 // CTA serves one species, all 4 l
    __shared__ float wsm[LMAX * SPBLK];       // 48 KB

    for (int t = threadIdx.x; t < LMAX * SPBLK; t += blockDim.x) {
        int l = t / SPBLK;
        int j = t - l * SPBLK;
        float v;
        if (j < 512)        v = W1[(l * NSPEC + s) * 512  + j];
        else if (j < 1536)  v = W2[(l * NSPEC + s) * 1024 + (j - 512)];
        else if (j < 2560)  v = W3[(l * NSPEC + s) * 1024 + (j - 1536)];
        else                v = W4[(l * NSPEC + s) * 512  + (j - 2560)];
        wsm[t] = v;
    }
    __syncthreads();

    const int beg = d_off[s];
    const int end = d_off[s + 1];

    for (int i = beg + blockIdx.x * blockDim.x + threadIdx.x; i < end;
         i += gridDim.x * blockDim.x) {
        const int idx = d_sorted[i];          // species-pure by construction

        // one pair, all 4 l's: x/out rows are 256B contiguous, L1-resident
#pragma unroll 1
        for (int l = 0; l < LMAX; ++l) {
            const float* w = &wsm[l * SPBLK];
            float a[HID], b[HID];

            const float4* xin = reinterpret_cast<const float4*>(
                xg + ((size_t)idx * LMAX + l) * NM);
#pragma unroll
            for (int q = 0; q < 4; ++q) {
                float4 v = xin[q];
                a[q * 4 + 0] = v.x; a[q * 4 + 1] = v.y;
                a[q * 4 + 2] = v.z; a[q * 4 + 3] = v.w;
            }

            layer2<NM,  HID, true >(w,        a, b);   // L1 + silu
            layer2<HID, HID, true >(w + 512,  b, a);   // L2 + silu
            layer2<HID, HID, true >(w + 1536, a, b);   // L3 + silu
            layer2<HID, NM,  false>(w + 2560, b, a);   // L4

            float4* op = reinterpret_cast<float4*>(
                out + ((size_t)idx * LMAX + l) * NM);
#pragma unroll
            for (int q = 0; q < 4; ++q)
                op[q] = make_float4(a[q * 4 + 0], a[q * 4 + 1],
                                    a[q * 4 + 2], a[q * 4 + 3]);
        }
    }
}

// ---------------- launch ----------------

extern "C" void kernel_launch(void* const* d_in, const int* in_sizes, int n_in,
                              void* d_out, int out_size) {
    const float* x   = (const float*)d_in[0];
    const int*   sp  = (const int*)d_in[1];   // int32 or int64 — detected on device
    const float* W1  = (const float*)d_in[2];
    const float* W2  = (const float*)d_in[3];
    const float* W3  = (const float*)d_in[4];
    const float* W4  = (const float*)d_in[5];
    float*       out = (float*)d_out;

    const int nblk = (N_PAIRS + 255) / 256;

    k_zero<<<1, 32>>>();
    k_hist<<<nblk, 256>>>(sp);
    k_offsets<<<1, 1>>>();
    k_scatter<<<nblk, 256>>>(sp);

    // grid (76, NSPEC) = 304 CTAs = 2/SM (reg-limited), one wave
    dim3 grid(76, NSPEC);
    k_mlp<<<grid, 256>>>(x, W1, W2, W3, W4, out);
}

// round 11
// speedup vs baseline: 2.3146x; 2.3146x over previous
#include <cuda_runtime.h>
#include <cuda_bf16.h>
#include <cstdint>

#define N_PAIRS 500000
#define LMAX    4
#define NM      16
#define HID     32
#define NSPEC   4
#define NTILES  24            // B-fragment tiles per (l,s): L1:4, L2:8, L3:8, L4:4

// Scratch (allocation-free rule: __device__ globals)
__device__ int d_count[NSPEC];
__device__ int d_cursor[NSPEC];
__device__ int d_off[NSPEC + 1];
__device__ int d_sorted[N_PAIRS];
// pre-distributed B fragments: [ls][hi/lo][tile*32 + lane] = {reg0, reg1}
__device__ uint2 d_wfrag[LMAX * NSPEC][2][NTILES * 32];

// ---------------- block-local species dtype detection ----------------
__device__ __forceinline__ int detect_stride(const int* __restrict__ sp32,
                                             int tid, int* shflag) {
    if (tid == 0) *shflag = 0;
    __syncthreads();
    if (tid < 256 && sp32[2 * tid + 1] != 0) atomicOr(shflag, 1);
    __syncthreads();
    return *shflag ? 1 : 2;
}

// ---------------- sort-by-species pipeline (proven) ----------------

__global__ void k_zero() {
    if (threadIdx.x < NSPEC) d_count[threadIdx.x] = 0;
}

__global__ void k_hist(const int* __restrict__ sp32) {
    __shared__ int cnt[NSPEC];
    __shared__ int flag;
    int tid = threadIdx.x;
    if (tid < NSPEC) cnt[tid] = 0;
    const int stride = detect_stride(sp32, tid, &flag);
    __syncthreads();
    int i = blockIdx.x * blockDim.x + tid;
    if (i < N_PAIRS) {
        int sp = sp32[i * stride] & 3;
        atomicAdd(&cnt[sp], 1);
    }
    __syncthreads();
    if (tid < NSPEC && cnt[tid] > 0) atomicAdd(&d_count[tid], cnt[tid]);
}

__global__ void k_offsets() {
    int acc = 0;
    for (int s = 0; s < NSPEC; ++s) {
        d_off[s] = acc;
        d_cursor[s] = acc;
        acc += d_count[s];
    }
    d_off[NSPEC] = acc;
}

__global__ void k_scatter(const int* __restrict__ sp32) {
    __shared__ int cnt[NSPEC];
    __shared__ int base[NSPEC];
    __shared__ int flag;
    int tid = threadIdx.x;
    if (tid < NSPEC) cnt[tid] = 0;
    const int stride = detect_stride(sp32, tid, &flag);
    __syncthreads();
    int i = blockIdx.x * blockDim.x + tid;
    int sp = 0;
    if (i < N_PAIRS) {
        sp = sp32[i * stride] & 3;
        atomicAdd(&cnt[sp], 1);
    }
    __syncthreads();
    if (tid < NSPEC) {
        base[tid] = (cnt[tid] > 0) ? atomicAdd(&d_cursor[tid], cnt[tid]) : 0;
        cnt[tid] = 0;
    }
    __syncthreads();
    if (i < N_PAIRS) {
        int r = atomicAdd(&cnt[sp], 1);
        d_sorted[base[sp] + r] = i;
    }
}

// ---------------- bf16 helpers ----------------

__device__ __forceinline__ uint32_t packbf(__nv_bfloat16 lo, __nv_bfloat16 hi) {
    __nv_bfloat162 t(lo, hi);      // .x = low 16 bits = element 0
    return *reinterpret_cast<uint32_t*>(&t);
}

// split (f0, f1) -> bf16x2 hi fragment reg + bf16x2 residual reg
__device__ __forceinline__ void splitpack(float f0, float f1,
                                          uint32_t& hi, uint32_t& lo) {
    __nv_bfloat16 h0 = __float2bfloat16(f0);
    __nv_bfloat16 h1 = __float2bfloat16(f1);
    hi = packbf(h0, h1);
    __nv_bfloat16 l0 = __float2bfloat16(f0 - __bfloat162float(h0));
    __nv_bfloat16 l1 = __float2bfloat16(f1 - __bfloat162float(h1));
    lo = packbf(l0, l1);
}

__device__ __forceinline__ float silu(float v) {
    return __fdividef(v, 1.0f + __expf(-v));
}

// ---------------- weight fragment prep ----------------
// B fragment (mma.m16n8k16, col-major B = W[k][n]):
//   lane: q = lane&3, col = lane>>2; k0 = ktile*16 + 2q; n = ntile*8 + col
//   reg0 = {W[k0][n], W[k0+1][n]}, reg1 = {W[k0+8][n], W[k0+9][n]}
// Tile order: L1: 0..3 (ntile, K=16); L2: 4 + n*2 + k; L3: 12 + n*2 + k;
//             L4: 20 + n*2 + k (ntile 0..1, W4 is [32][16]).

__global__ void k_prep(const float* __restrict__ W1, const float* __restrict__ W2,
                       const float* __restrict__ W3, const float* __restrict__ W4) {
    const int ls = blockIdx.x;
    for (int slot = threadIdx.x; slot < NTILES * 32; slot += blockDim.x) {
        const int tile = slot >> 5, lane = slot & 31;
        const int q = lane & 3, col = lane >> 2;
        const float* W;
        int N, nt, kt;
        if (tile < 4)       { W = W1 + ls * 512;  N = 32; nt = tile;           kt = 0; }
        else if (tile < 12) { W = W2 + ls * 1024; N = 32; nt = (tile-4)  >> 1; kt = (tile-4)  & 1; }
        else if (tile < 20) { W = W3 + ls * 1024; N = 32; nt = (tile-12) >> 1; kt = (tile-12) & 1; }
        else                { W = W4 + ls * 512;  N = 16; nt = (tile-20) >> 1; kt = (tile-20) & 1; }
        const int k0 = kt * 16 + q * 2;
        const int n  = nt * 8 + col;
        float e0 = W[(k0 + 0) * N + n], e1 = W[(k0 + 1) * N + n];
        float e2 = W[(k0 + 8) * N + n], e3 = W[(k0 + 9) * N + n];
        uint2 hi, lo;
        splitpack(e0, e1, hi.x, lo.x);
        splitpack(e2, e3, hi.y, lo.y);
        d_wfrag[ls][0][slot] = hi;
        d_wfrag[ls][1][slot] = lo;
    }
}

// ---------------- mma.sync (legacy HMMA, valid on plain sm_103 target) ----------------

__device__ __forceinline__ void mma16816(float* c, const uint32_t* a,
                                         uint32_t b0, uint32_t b1) {
    asm volatile(
        "mma.sync.aligned.m16n8k16.row.col.f32.bf16.bf16.f32 "
        "{%0,%1,%2,%3}, {%4,%5,%6,%7}, {%8,%9}, {%0,%1,%2,%3};"
        : "+f"(c[0]), "+f"(c[1]), "+f"(c[2]), "+f"(c[3])
        : "r"(a[0]), "r"(a[1]), "r"(a[2]), "r"(a[3]), "r"(b0), "r"(b1));
}

// C(m16n8) thread mapping == A(m16n8k16) k-halves: chain layers in registers.
// acc[4 ntiles][4] -> Ah/Al[2 ktiles][4] via silu + split (no shuffles).
__device__ __forceinline__ void epilogue(float acc[][4],
                                         uint32_t Ah[2][4], uint32_t Al[2][4]) {
#pragma unroll
    for (int j = 0; j < 2; ++j) {
        float s00 = silu(acc[2*j][0]),   s01 = silu(acc[2*j][1]);
        float s02 = silu(acc[2*j][2]),   s03 = silu(acc[2*j][3]);
        float s10 = silu(acc[2*j+1][0]), s11 = silu(acc[2*j+1][1]);
        float s12 = silu(acc[2*j+1][2]), s13 = silu(acc[2*j+1][3]);
        splitpack(s00, s01, Ah[j][0], Al[j][0]);
        splitpack(s02, s03, Ah[j][1], Al[j][1]);
        splitpack(s10, s11, Ah[j][2], Al[j][2]);
        splitpack(s12, s13, Ah[j][3], Al[j][3]);
    }
}

// ---------------- main MLP kernel ----------------

__global__ void __launch_bounds__(256, 2)
k_mlp(const float* __restrict__ xg, float* __restrict__ out) {
    const int ls = blockIdx.y;
    const int l = ls >> 2, s = ls & 3;

    __shared__ uint2 whi[NTILES * 32], wlo[NTILES * 32];
    for (int i = threadIdx.x; i < NTILES * 32; i += 256) {
        whi[i] = d_wfrag[ls][0][i];
        wlo[i] = d_wfrag[ls][1][i];
    }
    __syncthreads();

    const int lane = threadIdx.x & 31, wid = threadIdx.x >> 5;
    const int q = lane & 3, g = lane >> 2;
    const int beg = d_off[s], cnt = d_count[s];
    const int ntile = (cnt + 15) >> 4;

    for (int t = blockIdx.x * 8 + wid; t < ntile; t += gridDim.x * 8) {
        int r0 = t * 16 + g;     if (r0 >= cnt) r0 = cnt - 1;
        int r1 = t * 16 + g + 8; if (r1 >= cnt) r1 = cnt - 1;
        const int i0 = d_sorted[beg + r0];
        const int i1 = d_sorted[beg + r1];
        const float* p0 = xg + (size_t)i0 * (LMAX * NM) + l * NM;
        const float* p1 = xg + (size_t)i1 * (LMAX * NM) + l * NM;

        // A fragment: rows {g, g+8}, cols {2q,2q+1} and {2q+8,2q+9}
        float2 v00 = *reinterpret_cast<const float2*>(p0 + 2 * q);
        float2 v01 = *reinterpret_cast<const float2*>(p0 + 2 * q + 8);
        float2 v10 = *reinterpret_cast<const float2*>(p1 + 2 * q);
        float2 v11 = *reinterpret_cast<const float2*>(p1 + 2 * q + 8);

        uint32_t Ah[2][4], Al[2][4];
        splitpack(v00.x, v00.y, Ah[0][0], Al[0][0]);
        splitpack(v10.x, v10.y, Ah[0][1], Al[0][1]);
        splitpack(v01.x, v01.y, Ah[0][2], Al[0][2]);
        splitpack(v11.x, v11.y, Ah[0][3], Al[0][3]);

        float acc[4][4];

        // ---- L1: K=16, tiles 0..3 (3-term split: hi*Wh + lo*Wh + hi*Wl) ----
#pragma unroll
        for (int n = 0; n < 4; ++n) {
#pragma unroll
            for (int e = 0; e < 4; ++e) acc[n][e] = 0.f;
            uint2 bh = whi[n * 32 + lane];
            uint2 bl = wlo[n * 32 + lane];
            mma16816(acc[n], Ah[0], bh.x, bh.y);
            mma16816(acc[n], Al[0], bh.x, bh.y);
            mma16816(acc[n], Ah[0], bl.x, bl.y);
        }
        epilogue(acc, Ah, Al);

        // ---- L2, L3: K=32, tiles 4.. and 12.. ----
#pragma unroll
        for (int base = 4; base <= 12; base += 8) {
#pragma unroll
            for (int n = 0; n < 4; ++n) {
#pragma unroll
                for (int e = 0; e < 4; ++e) acc[n][e] = 0.f;
#pragma unroll
                for (int k = 0; k < 2; ++k) {
                    uint2 bh = whi[(base + n * 2 + k) * 32 + lane];
                    uint2 bl = wlo[(base + n * 2 + k) * 32 + lane];
                    mma16816(acc[n], Ah[k], bh.x, bh.y);
                    mma16816(acc[n], Al[k], bh.x, bh.y);
                    mma16816(acc[n], Ah[k], bl.x, bl.y);
                }
            }
            epilogue(acc, Ah, Al);
        }

        // ---- L4: K=32, N=16, tiles 20..23 ----
#pragma unroll
        for (int n = 0; n < 2; ++n) {
#pragma unroll
            for (int e = 0; e < 4; ++e) acc[n][e] = 0.f;
#pragma unroll
            for (int k = 0; k < 2; ++k) {
                uint2 bh = whi[(20 + n * 2 + k) * 32 + lane];
                uint2 bl = wlo[(20 + n * 2 + k) * 32 + lane];
                mma16816(acc[n], Ah[k], bh.x, bh.y);
                mma16816(acc[n], Al[k], bh.x, bh.y);
                mma16816(acc[n], Ah[k], bl.x, bl.y);
            }
        }

        // ---- write out: C(m16n8) mapping, 2 rows x 2 ntiles x float2 ----
        float* o0 = out + (size_t)i0 * (LMAX * NM) + l * NM;
        float* o1 = out + (size_t)i1 * (LMAX * NM) + l * NM;
        *reinterpret_cast<float2*>(o0 + 2 * q)     = make_float2(acc[0][0], acc[0][1]);
        *reinterpret_cast<float2*>(o0 + 2 * q + 8) = make_float2(acc[1][0], acc[1][1]);
        *reinterpret_cast<float2*>(o1 + 2 * q)     = make_float2(acc[0][2], acc[0][3]);
        *reinterpret_cast<float2*>(o1 + 2 * q + 8) = make_float2(acc[1][2], acc[1][3]);
    }
}

// ---------------- launch ----------------

extern "C" void kernel_launch(void* const* d_in, const int* in_sizes, int n_in,
                              void* d_out, int out_size) {
    const float* x   = (const float*)d_in[0];
    const int*   sp  = (const int*)d_in[1];   // int32 or int64 — detected on device
    const float* W1  = (const float*)d_in[2];
    const float* W2  = (const float*)d_in[3];
    const float* W3  = (const float*)d_in[4];
    const float* W4  = (const float*)d_in[5];
    float*       out = (float*)d_out;

    const int nblk = (N_PAIRS + 255) / 256;

    k_zero<<<1, 32>>>();
    k_hist<<<nblk, 256>>>(sp);
    k_offsets<<<1, 1>>>();
    k_scatter<<<nblk, 256>>>(sp);
    k_prep<<<LMAX * NSPEC, 128>>>(W1, W2, W3, W4);

    // 40 x 16 = 640 CTAs (2/SM resident), 8 warps each, warp = 16-pair tile
    dim3 grid(40, LMAX * NSPEC);
    k_mlp<<<grid, 256>>>(x, out);
}

// round 12
// speedup vs baseline: 2.7507x; 1.1884x over previous
#include <cuda_runtime.h>
#include <cuda_bf16.h>
#include <cstdint>

#define N_PAIRS 500000
#define LMAX    4
#define NM      16
#define HID     32
#define NSPEC   4
#define NTILES  24            // B-fragment tiles per (l,s): L1:4, L2:8, L3:8, L4:4

// Scratch (allocation-free rule: __device__ globals)
__device__ int d_count[NSPEC];
__device__ int d_cursor[NSPEC];
__device__ int d_sorted[N_PAIRS];

// ---------------- block-local species dtype detection ----------------
__device__ __forceinline__ int detect_stride(const int* __restrict__ sp32,
                                             int tid, int* shflag) {
    if (tid == 0) *shflag = 0;
    __syncthreads();
    if (tid < 256 && sp32[2 * tid + 1] != 0) atomicOr(shflag, 1);
    __syncthreads();
    return *shflag ? 1 : 2;
}

// ---------------- sort-by-species (4 launches total incl. mlp) ----------------

__global__ void k_zero() {
    if (threadIdx.x < NSPEC) {
        d_count[threadIdx.x] = 0;
        d_cursor[threadIdx.x] = 0;
    }
}

__global__ void k_hist(const int* __restrict__ sp32) {
    __shared__ int cnt[NSPEC];
    __shared__ int flag;
    int tid = threadIdx.x;
    if (tid < NSPEC) cnt[tid] = 0;
    const int stride = detect_stride(sp32, tid, &flag);
    __syncthreads();
    int i = blockIdx.x * blockDim.x + tid;
    if (i < N_PAIRS) {
        int sp = sp32[i * stride] & 3;
        atomicAdd(&cnt[sp], 1);
    }
    __syncthreads();
    if (tid < NSPEC && cnt[tid] > 0) atomicAdd(&d_count[tid], cnt[tid]);
}

// scatter derives bucket offsets locally from d_count (no k_offsets launch)
__global__ void k_scatter(const int* __restrict__ sp32) {
    __shared__ int cnt[NSPEC];
    __shared__ int base[NSPEC];
    __shared__ int flag;
    int tid = threadIdx.x;
    if (tid < NSPEC) cnt[tid] = 0;
    const int stride = detect_stride(sp32, tid, &flag);
    __syncthreads();
    int i = blockIdx.x * blockDim.x + tid;
    int sp = 0;
    if (i < N_PAIRS) {
        sp = sp32[i * stride] & 3;
        atomicAdd(&cnt[sp], 1);
    }
    __syncthreads();
    if (tid < NSPEC) {
        int off = 0;                       // exclusive prefix of d_count[0..tid)
        for (int s = 0; s < tid; ++s) off += d_count[s];
        base[tid] = (cnt[tid] > 0) ? off + atomicAdd(&d_cursor[tid], cnt[tid]) : 0;
        cnt[tid] = 0;                      // reuse as local rank cursor
    }
    __syncthreads();
    if (i < N_PAIRS) {
        int r = atomicAdd(&cnt[sp], 1);
        d_sorted[base[sp] + r] = i;
    }
}

// ---------------- bf16 split helpers ----------------

// split (f0, f1) -> bf16x2 hi reg (lo half = f0) + bf16x2 residual reg
__device__ __forceinline__ void splitpack(float f0, float f1,
                                          uint32_t& hi, uint32_t& lo) {
    asm("cvt.rn.bf16x2.f32 %0, %2, %1;" : "=r"(hi) : "f"(f0), "f"(f1));
    uint32_t u0 = hi << 16;
    uint32_t u1 = hi & 0xFFFF0000u;
    float r0 = f0 - __uint_as_float(u0);
    float r1 = f1 - __uint_as_float(u1);
    asm("cvt.rn.bf16x2.f32 %0, %2, %1;" : "=r"(lo) : "f"(r0), "f"(r1));
}

__device__ __forceinline__ float silu(float v) {
    return __fdividef(v, 1.0f + __expf(-v));
}

// ---------------- mma.sync (legacy HMMA, valid on plain sm_103 target) ----------------

__device__ __forceinline__ void mma16816(float* c, const uint32_t* a,
                                         uint32_t b0, uint32_t b1) {
    asm volatile(
        "mma.sync.aligned.m16n8k16.row.col.f32.bf16.bf16.f32 "
        "{%0,%1,%2,%3}, {%4,%5,%6,%7}, {%8,%9}, {%0,%1,%2,%3};"
        : "+f"(c[0]), "+f"(c[1]), "+f"(c[2]), "+f"(c[3])
        : "r"(a[0]), "r"(a[1]), "r"(a[2]), "r"(a[3]), "r"(b0), "r"(b1));
}

// C(m16n8) thread mapping == A(m16n8k16) k-halves: chain layers in registers.
__device__ __forceinline__ void epilogue(float acc[][4],
                                         uint32_t Ah[2][4], uint32_t Al[2][4]) {
#pragma unroll
    for (int j = 0; j < 2; ++j) {
        float s00 = silu(acc[2*j][0]),   s01 = silu(acc[2*j][1]);
        float s02 = silu(acc[2*j][2]),   s03 = silu(acc[2*j][3]);
        float s10 = silu(acc[2*j+1][0]), s11 = silu(acc[2*j+1][1]);
        float s12 = silu(acc[2*j+1][2]), s13 = silu(acc[2*j+1][3]);
        splitpack(s00, s01, Ah[j][0], Al[j][0]);
        splitpack(s02, s03, Ah[j][1], Al[j][1]);
        splitpack(s10, s11, Ah[j][2], Al[j][2]);
        splitpack(s12, s13, Ah[j][3], Al[j][3]);
    }
}

// ---------------- main MLP kernel (fragment prep fused in) ----------------
// B fragment (mma.m16n8k16, col-major B = W[k][n]):
//   lane: q = lane&3, col = lane>>2; k0 = ktile*16 + 2q; n = ntile*8 + col
//   reg0 = {W[k0][n], W[k0+1][n]}, reg1 = {W[k0+8][n], W[k0+9][n]}
// Tile order: L1: 0..3 (ntile, K=16); L2: 4 + n*2 + k; L3: 12 + n*2 + k;
//             L4: 20 + n*2 + k (ntile 0..1, W4 is [32][16]).

__global__ void __launch_bounds__(256, 3)
k_mlp(const float* __restrict__ xg,
      const float* __restrict__ W1, const float* __restrict__ W2,
      const float* __restrict__ W3, const float* __restrict__ W4,
      float* __restrict__ out) {
    const int ls = blockIdx.y;
    const int l = ls >> 2, s = ls & 3;

    __shared__ uint2 whi[NTILES * 32], wlo[NTILES * 32];

    // fused fragment prep: each CTA builds its (l,s) fragments into smem
    for (int slot = threadIdx.x; slot < NTILES * 32; slot += 256) {
        const int tile = slot >> 5, lane = slot & 31;
        const int q = lane & 3, col = lane >> 2;
        const float* W;
        int N, nt, kt;
        if (tile < 4)       { W = W1 + ls * 512;  N = 32; nt = tile;           kt = 0; }
        else if (tile < 12) { W = W2 + ls * 1024; N = 32; nt = (tile-4)  >> 1; kt = (tile-4)  & 1; }
        else if (tile < 20) { W = W3 + ls * 1024; N = 32; nt = (tile-12) >> 1; kt = (tile-12) & 1; }
        else                { W = W4 + ls * 512;  N = 16; nt = (tile-20) >> 1; kt = (tile-20) & 1; }
        const int k0 = kt * 16 + q * 2;
        const int n  = nt * 8 + col;
        float e0 = W[(k0 + 0) * N + n], e1 = W[(k0 + 1) * N + n];
        float e2 = W[(k0 + 8) * N + n], e3 = W[(k0 + 9) * N + n];
        uint2 hi, lo;
        splitpack(e0, e1, hi.x, lo.x);
        splitpack(e2, e3, hi.y, lo.y);
        whi[slot] = hi;
        wlo[slot] = lo;
    }

    // bucket offset + count from d_count (local prefix over <=4)
    int beg = 0;
#pragma unroll
    for (int t = 0; t < NSPEC; ++t) if (t < s) beg += d_count[t];
    const int cnt = d_count[s];
    __syncthreads();

    const int lane = threadIdx.x & 31, wid = threadIdx.x >> 5;
    const int q = lane & 3, g = lane >> 2;
    const int ntile = (cnt + 15) >> 4;

    for (int t = blockIdx.x * 8 + wid; t < ntile; t += gridDim.x * 8) {
        int r0 = t * 16 + g;     if (r0 >= cnt) r0 = cnt - 1;
        int r1 = t * 16 + g + 8; if (r1 >= cnt) r1 = cnt - 1;
        const int i0 = d_sorted[beg + r0];
        const int i1 = d_sorted[beg + r1];
        const float* p0 = xg + (size_t)i0 * (LMAX * NM) + l * NM;
        const float* p1 = xg + (size_t)i1 * (LMAX * NM) + l * NM;

        // A fragment: rows {g, g+8}, cols {2q,2q+1} and {2q+8,2q+9}
        float2 v00 = *reinterpret_cast<const float2*>(p0 + 2 * q);
        float2 v01 = *reinterpret_cast<const float2*>(p0 + 2 * q + 8);
        float2 v10 = *reinterpret_cast<const float2*>(p1 + 2 * q);
        float2 v11 = *reinterpret_cast<const float2*>(p1 + 2 * q + 8);

        uint32_t Ah[2][4], Al[2][4];
        splitpack(v00.x, v00.y, Ah[0][0], Al[0][0]);
        splitpack(v10.x, v10.y, Ah[0][1], Al[0][1]);
        splitpack(v01.x, v01.y, Ah[0][2], Al[0][2]);
        splitpack(v11.x, v11.y, Ah[0][3], Al[0][3]);

        float acc[4][4];

        // ---- L1: K=16, tiles 0..3 (3-term split: hi*Wh + lo*Wh + hi*Wl) ----
#pragma unroll
        for (int n = 0; n < 4; ++n) {
#pragma unroll
            for (int e = 0; e < 4; ++e) acc[n][e] = 0.f;
            uint2 bh = whi[n * 32 + lane];
            uint2 bl = wlo[n * 32 + lane];
            mma16816(acc[n], Ah[0], bh.x, bh.y);
            mma16816(acc[n], Al[0], bh.x, bh.y);
            mma16816(acc[n], Ah[0], bl.x, bl.y);
        }
        epilogue(acc, Ah, Al);

        // ---- L2, L3: K=32, tiles 4.. and 12.. ----
#pragma unroll
        for (int base = 4; base <= 12; base += 8) {
#pragma unroll
            for (int n = 0; n < 4; ++n) {
#pragma unroll
                for (int e = 0; e < 4; ++e) acc[n][e] = 0.f;
#pragma unroll
                for (int k = 0; k < 2; ++k) {
                    uint2 bh = whi[(base + n * 2 + k) * 32 + lane];
                    uint2 bl = wlo[(base + n * 2 + k) * 32 + lane];
                    mma16816(acc[n], Ah[k], bh.x, bh.y);
                    mma16816(acc[n], Al[k], bh.x, bh.y);
                    mma16816(acc[n], Ah[k], bl.x, bl.y);
                }
            }
            epilogue(acc, Ah, Al);
        }

        // ---- L4: K=32, N=16, tiles 20..23 ----
#pragma unroll
        for (int n = 0; n < 2; ++n) {
#pragma unroll
            for (int e = 0; e < 4; ++e) acc[n][e] = 0.f;
#pragma unroll
            for (int k = 0; k < 2; ++k) {
                uint2 bh = whi[(20 + n * 2 + k) * 32 + lane];
                uint2 bl = wlo[(20 + n * 2 + k) * 32 + lane];
                mma16816(acc[n], Ah[k], bh.x, bh.y);
                mma16816(acc[n], Al[k], bh.x, bh.y);
                mma16816(acc[n], Ah[k], bl.x, bl.y);
            }
        }

        // ---- write out: C(m16n8) mapping, 2 rows x 2 ntiles x float2 ----
        float* o0 = out + (size_t)i0 * (LMAX * NM) + l * NM;
        float* o1 = out + (size_t)i1 * (LMAX * NM) + l * NM;
        *reinterpret_cast<float2*>(o0 + 2 * q)     = make_float2(acc[0][0], acc[0][1]);
        *reinterpret_cast<float2*>(o0 + 2 * q + 8) = make_float2(acc[1][0], acc[1][1]);
        *reinterpret_cast<float2*>(o1 + 2 * q)     = make_float2(acc[0][2], acc[0][3]);
        *reinterpret_cast<float2*>(o1 + 2 * q + 8) = make_float2(acc[1][2], acc[1][3]);
    }
}

// ---------------- launch ----------------

extern "C" void kernel_launch(void* const* d_in, const int* in_sizes, int n_in,
                              void* d_out, int out_size) {
    const float* x   = (const float*)d_in[0];
    const int*   sp  = (const int*)d_in[1];   // int32 or int64 — detected on device
    const float* W1  = (const float*)d_in[2];
    const float* W2  = (const float*)d_in[3];
    const float* W3  = (const float*)d_in[4];
    const float* W4  = (const float*)d_in[5];
    float*       out = (float*)d_out;

    const int nblk = (N_PAIRS + 255) / 256;

    k_zero<<<1, 32>>>();
    k_hist<<<nblk, 256>>>(sp);
    k_scatter<<<nblk, 256>>>(sp);

    // 40 x 16 = 640 CTAs, 8 warps each; k_mlp is launch #4 (profiler slot)
    dim3 grid(40, LMAX * NSPEC);
    k_mlp<<<grid, 256>>>(x, W1, W2, W3, W4, out);
}

// round 13
// speedup vs baseline: 3.4546x; 1.2559x over previous
#include <cuda_runtime.h>
#include <cuda_bf16.h>
#include <cstdint>

#define N_PAIRS 500000
#define LMAX    4
#define NM      16
#define HID     32
#define NSPEC   4
#define NTILES  24            // B-fragment tiles per (l,s): L1:4, L2:8, L3:8, L4:4

// Scratch (allocation-free rule: __device__ globals)
__device__ int d_count[NSPEC];
__device__ int d_cursor[NSPEC];
__device__ int d_sorted[N_PAIRS];

// ---------------- block-local species dtype detection ----------------
__device__ __forceinline__ int detect_stride(const int* __restrict__ sp32,
                                             int tid, int* shflag) {
    if (tid == 0) *shflag = 0;
    __syncthreads();
    if (tid < 256 && sp32[2 * tid + 1] != 0) atomicOr(shflag, 1);
    __syncthreads();
    return *shflag ? 1 : 2;
}

// ---------------- sort-by-species (4 launches total incl. mlp) ----------------

__global__ void k_zero() {
    if (threadIdx.x < NSPEC) {
        d_count[threadIdx.x] = 0;
        d_cursor[threadIdx.x] = 0;
    }
}

__global__ void k_hist(const int* __restrict__ sp32) {
    __shared__ int cnt[NSPEC];
    __shared__ int flag;
    int tid = threadIdx.x;
    if (tid < NSPEC) cnt[tid] = 0;
    const int stride = detect_stride(sp32, tid, &flag);
    __syncthreads();
    int i = blockIdx.x * blockDim.x + tid;
    if (i < N_PAIRS) {
        int sp = sp32[i * stride] & 3;
        atomicAdd(&cnt[sp], 1);
    }
    __syncthreads();
    if (tid < NSPEC && cnt[tid] > 0) atomicAdd(&d_count[tid], cnt[tid]);
}

// scatter derives bucket offsets locally from d_count (no k_offsets launch)
__global__ void k_scatter(const int* __restrict__ sp32) {
    __shared__ int cnt[NSPEC];
    __shared__ int base[NSPEC];
    __shared__ int flag;
    int tid = threadIdx.x;
    if (tid < NSPEC) cnt[tid] = 0;
    const int stride = detect_stride(sp32, tid, &flag);
    __syncthreads();
    int i = blockIdx.x * blockDim.x + tid;
    int sp = 0;
    if (i < N_PAIRS) {
        sp = sp32[i * stride] & 3;
        atomicAdd(&cnt[sp], 1);
    }
    __syncthreads();
    if (tid < NSPEC) {
        int off = 0;                       // exclusive prefix of d_count[0..tid)
        for (int s = 0; s < tid; ++s) off += d_count[s];
        base[tid] = (cnt[tid] > 0) ? off + atomicAdd(&d_cursor[tid], cnt[tid]) : 0;
        cnt[tid] = 0;                      // reuse as local rank cursor
    }
    __syncthreads();
    if (i < N_PAIRS) {
        int r = atomicAdd(&cnt[sp], 1);
        d_sorted[base[sp] + r] = i;
    }
}

// ---------------- bf16 split helpers ----------------

// split (f0, f1) -> bf16x2 hi reg (lo half = f0) + bf16x2 residual reg
__device__ __forceinline__ void splitpack(float f0, float f1,
                                          uint32_t& hi, uint32_t& lo) {
    asm("cvt.rn.bf16x2.f32 %0, %2, %1;" : "=r"(hi) : "f"(f0), "f"(f1));
    uint32_t u0 = hi << 16;
    uint32_t u1 = hi & 0xFFFF0000u;
    float r0 = f0 - __uint_as_float(u0);
    float r1 = f1 - __uint_as_float(u1);
    asm("cvt.rn.bf16x2.f32 %0, %2, %1;" : "=r"(lo) : "f"(r0), "f"(r1));
}

// silu via tanh.approx (1 MUFU op instead of 2):
// silu(v) = 0.5*v*(1 + tanh(v/2)) = fma(0.5v, tanh(0.5v), 0.5v)
__device__ __forceinline__ float silu(float v) {
    float h = 0.5f * v;
    float t;
    asm("tanh.approx.f32 %0, %1;" : "=f"(t) : "f"(h));
    return fmaf(h, t, h);
}

// ---------------- mma.sync (legacy HMMA, valid on plain sm_103 target) ----------------

__device__ __forceinline__ void mma16816(float* c, const uint32_t* a,
                                         uint32_t b0, uint32_t b1) {
    asm volatile(
        "mma.sync.aligned.m16n8k16.row.col.f32.bf16.bf16.f32 "
        "{%0,%1,%2,%3}, {%4,%5,%6,%7}, {%8,%9}, {%0,%1,%2,%3};"
        : "+f"(c[0]), "+f"(c[1]), "+f"(c[2]), "+f"(c[3])
        : "r"(a[0]), "r"(a[1]), "r"(a[2]), "r"(a[3]), "r"(b0), "r"(b1));
}

// C(m16n8) thread mapping == A(m16n8k16) k-halves: chain layers in registers.
__device__ __forceinline__ void epilogue(float acc[][4],
                                         uint32_t Ah[2][4], uint32_t Al[2][4]) {
#pragma unroll
    for (int j = 0; j < 2; ++j) {
        float s00 = silu(acc[2*j][0]),   s01 = silu(acc[2*j][1]);
        float s02 = silu(acc[2*j][2]),   s03 = silu(acc[2*j][3]);
        float s10 = silu(acc[2*j+1][0]), s11 = silu(acc[2*j+1][1]);
        float s12 = silu(acc[2*j+1][2]), s13 = silu(acc[2*j+1][3]);
        splitpack(s00, s01, Ah[j][0], Al[j][0]);
        splitpack(s02, s03, Ah[j][1], Al[j][1]);
        splitpack(s10, s11, Ah[j][2], Al[j][2]);
        splitpack(s12, s13, Ah[j][3], Al[j][3]);
    }
}

// ---------------- main MLP kernel (fragment prep fused in) ----------------
// B fragment (mma.m16n8k16, col-major B = W[k][n]):
//   lane: q = lane&3, col = lane>>2; k0 = ktile*16 + 2q; n = ntile*8 + col
//   reg0 = {W[k0][n], W[k0+1][n]}, reg1 = {W[k0+8][n], W[k0+9][n]}
// Tile order: L1: 0..3 (ntile, K=16); L2: 4 + n*2 + k; L3: 12 + n*2 + k;
//             L4: 20 + n*2 + k (ntile 0..1, W4 is [32][16]).

__global__ void __launch_bounds__(256, 3)
k_mlp(const float* __restrict__ xg,
      const float* __restrict__ W1, const float* __restrict__ W2,
      const float* __restrict__ W3, const float* __restrict__ W4,
      float* __restrict__ out) {
    const int ls = blockIdx.y;
    const int l = ls >> 2, s = ls & 3;

    __shared__ uint2 whi[NTILES * 32], wlo[NTILES * 32];

    // fused fragment prep: each CTA builds its (l,s) fragments into smem
    for (int slot = threadIdx.x; slot < NTILES * 32; slot += 256) {
        const int tile = slot >> 5, lane = slot & 31;
        const int q = lane & 3, col = lane >> 2;
        const float* W;
        int N, nt, kt;
        if (tile < 4)       { W = W1 + ls * 512;  N = 32; nt = tile;           kt = 0; }
        else if (tile < 12) { W = W2 + ls * 1024; N = 32; nt = (tile-4)  >> 1; kt = (tile-4)  & 1; }
        else if (tile < 20) { W = W3 + ls * 1024; N = 32; nt = (tile-12) >> 1; kt = (tile-12) & 1; }
        else                { W = W4 + ls * 512;  N = 16; nt = (tile-20) >> 1; kt = (tile-20) & 1; }
        const int k0 = kt * 16 + q * 2;
        const int n  = nt * 8 + col;
        float e0 = W[(k0 + 0) * N + n], e1 = W[(k0 + 1) * N + n];
        float e2 = W[(k0 + 8) * N + n], e3 = W[(k0 + 9) * N + n];
        uint2 hi, lo;
        splitpack(e0, e1, hi.x, lo.x);
        splitpack(e2, e3, hi.y, lo.y);
        whi[slot] = hi;
        wlo[slot] = lo;
    }

    // bucket offset + count from d_count (local prefix over <=4)
    int beg = 0;
#pragma unroll
    for (int t = 0; t < NSPEC; ++t) if (t < s) beg += d_count[t];
    const int cnt = d_count[s];
    __syncthreads();

    const int lane = threadIdx.x & 31, wid = threadIdx.x >> 5;
    const int q = lane & 3, g = lane >> 2;
    const int ntile = (cnt + 15) >> 4;

    for (int t = blockIdx.x * 8 + wid; t < ntile; t += gridDim.x * 8) {
        int r0 = t * 16 + g;     if (r0 >= cnt) r0 = cnt - 1;
        int r1 = t * 16 + g + 8; if (r1 >= cnt) r1 = cnt - 1;
        const int i0 = d_sorted[beg + r0];
        const int i1 = d_sorted[beg + r1];
        const float* p0 = xg + (size_t)i0 * (LMAX * NM) + l * NM;
        const float* p1 = xg + (size_t)i1 * (LMAX * NM) + l * NM;

        // A fragment: rows {g, g+8}, cols {2q,2q+1} and {2q+8,2q+9}
        float2 v00 = *reinterpret_cast<const float2*>(p0 + 2 * q);
        float2 v01 = *reinterpret_cast<const float2*>(p0 + 2 * q + 8);
        float2 v10 = *reinterpret_cast<const float2*>(p1 + 2 * q);
        float2 v11 = *reinterpret_cast<const float2*>(p1 + 2 * q + 8);

        uint32_t Ah[2][4], Al[2][4];
        splitpack(v00.x, v00.y, Ah[0][0], Al[0][0]);
        splitpack(v10.x, v10.y, Ah[0][1], Al[0][1]);
        splitpack(v01.x, v01.y, Ah[0][2], Al[0][2]);
        splitpack(v11.x, v11.y, Ah[0][3], Al[0][3]);

        float acc[4][4];

        // ---- L1: K=16, tiles 0..3 (3-term split: hi*Wh + lo*Wh + hi*Wl) ----
#pragma unroll
        for (int n = 0; n < 4; ++n) {
#pragma unroll
            for (int e = 0; e < 4; ++e) acc[n][e] = 0.f;
            uint2 bh = whi[n * 32 + lane];
            uint2 bl = wlo[n * 32 + lane];
            mma16816(acc[n], Ah[0], bh.x, bh.y);
            mma16816(acc[n], Al[0], bh.x, bh.y);
            mma16816(acc[n], Ah[0], bl.x, bl.y);
        }
        epilogue(acc, Ah, Al);

        // ---- L2, L3: K=32, tiles 4.. and 12.. ----
#pragma unroll
        for (int base = 4; base <= 12; base += 8) {
#pragma unroll
            for (int n = 0; n < 4; ++n) {
#pragma unroll
                for (int e = 0; e < 4; ++e) acc[n][e] = 0.f;
#pragma unroll
                for (int k = 0; k < 2; ++k) {
                    uint2 bh = whi[(base + n * 2 + k) * 32 + lane];
                    uint2 bl = wlo[(base + n * 2 + k) * 32 + lane];
                    mma16816(acc[n], Ah[k], bh.x, bh.y);
                    mma16816(acc[n], Al[k], bh.x, bh.y);
                    mma16816(acc[n], Ah[k], bl.x, bl.y);
                }
            }
            epilogue(acc, Ah, Al);
        }

        // ---- L4: K=32, N=16, tiles 20..23 ----
#pragma unroll
        for (int n = 0; n < 2; ++n) {
#pragma unroll
            for (int e = 0; e < 4; ++e) acc[n][e] = 0.f;
#pragma unroll
            for (int k = 0; k < 2; ++k) {
                uint2 bh = whi[(20 + n * 2 + k) * 32 + lane];
                uint2 bl = wlo[(20 + n * 2 + k) * 32 + lane];
                mma16816(acc[n], Ah[k], bh.x, bh.y);
                mma16816(acc[n], Al[k], bh.x, bh.y);
                mma16816(acc[n], Ah[k], bl.x, bl.y);
            }
        }

        // ---- write out: C(m16n8) mapping, 2 rows x 2 ntiles x float2 ----
        float* o0 = out + (size_t)i0 * (LMAX * NM) + l * NM;
        float* o1 = out + (size_t)i1 * (LMAX * NM) + l * NM;
        *reinterpret_cast<float2*>(o0 + 2 * q)     = make_float2(acc[0][0], acc[0][1]);
        *reinterpret_cast<float2*>(o0 + 2 * q + 8) = make_float2(acc[1][0], acc[1][1]);
        *reinterpret_cast<float2*>(o1 + 2 * q)     = make_float2(acc[0][2], acc[0][3]);
        *reinterpret_cast<float2*>(o1 + 2 * q + 8) = make_float2(acc[1][2], acc[1][3]);
    }
}

// ---------------- launch ----------------

extern "C" void kernel_launch(void* const* d_in, const int* in_sizes, int n_in,
                              void* d_out, int out_size) {
    const float* x   = (const float*)d_in[0];
    const int*   sp  = (const int*)d_in[1];   // int32 or int64 — detected on device
    const float* W1  = (const float*)d_in[2];
    const float* W2  = (const float*)d_in[3];
    const float* W3  = (const float*)d_in[4];
    const float* W4  = (const float*)d_in[5];
    float*       out = (float*)d_out;

    const int nblk = (N_PAIRS + 255) / 256;

    k_zero<<<1, 32>>>();
    k_hist<<<nblk, 256>>>(sp);
    k_scatter<<<nblk, 256>>>(sp);

    // 27 x 16 = 432 CTAs ~= one full wave at 3 CTAs/SM; 8 warps per CTA
    dim3 grid(27, LMAX * NSPEC);
    k_mlp<<<grid, 256>>>(x, W1, W2, W3, W4, out);
}

// round 14
// speedup vs baseline: 3.6098x; 1.0449x over previous
#include <cuda_runtime.h>
#include <cuda_bf16.h>
#include <cstdint>

#define N_PAIRS 500000
#define LMAX    4
#define NM      16
#define HID     32
#define NSPEC   4
#define NTILES  24            // B-fragment tiles per (l,s): L1:4, L2:8, L3:8, L4:4

// Scratch (allocation-free rule: __device__ globals)
__device__ int d_count[NSPEC];
__device__ int d_cursor[NSPEC];
__device__ int d_sorted[N_PAIRS];

// ---------------- block-local species dtype detection ----------------
__device__ __forceinline__ int detect_stride(const int* __restrict__ sp32,
                                             int tid, int* shflag) {
    if (tid == 0) *shflag = 0;
    __syncthreads();
    if (tid < 256 && sp32[2 * tid + 1] != 0) atomicOr(shflag, 1);
    __syncthreads();
    return *shflag ? 1 : 2;
}

// ---------------- sort-by-species (4 launches total incl. mlp) ----------------

__global__ void k_zero() {
    if (threadIdx.x < NSPEC) {
        d_count[threadIdx.x] = 0;
        d_cursor[threadIdx.x] = 0;
    }
}

__global__ void k_hist(const int* __restrict__ sp32) {
    __shared__ int cnt[NSPEC];
    __shared__ int flag;
    int tid = threadIdx.x;
    if (tid < NSPEC) cnt[tid] = 0;
    const int stride = detect_stride(sp32, tid, &flag);
    __syncthreads();
    int i = blockIdx.x * blockDim.x + tid;
    if (i < N_PAIRS) {
        int sp = sp32[i * stride] & 3;
        atomicAdd(&cnt[sp], 1);
    }
    __syncthreads();
    if (tid < NSPEC && cnt[tid] > 0) atomicAdd(&d_count[tid], cnt[tid]);
}

// scatter derives bucket offsets locally from d_count (no k_offsets launch)
__global__ void k_scatter(const int* __restrict__ sp32) {
    __shared__ int cnt[NSPEC];
    __shared__ int base[NSPEC];
    __shared__ int flag;
    int tid = threadIdx.x;
    if (tid < NSPEC) cnt[tid] = 0;
    const int stride = detect_stride(sp32, tid, &flag);
    __syncthreads();
    int i = blockIdx.x * blockDim.x + tid;
    int sp = 0;
    if (i < N_PAIRS) {
        sp = sp32[i * stride] & 3;
        atomicAdd(&cnt[sp], 1);
    }
    __syncthreads();
    if (tid < NSPEC) {
        int off = 0;                       // exclusive prefix of d_count[0..tid)
        for (int s = 0; s < tid; ++s) off += d_count[s];
        base[tid] = (cnt[tid] > 0) ? off + atomicAdd(&d_cursor[tid], cnt[tid]) : 0;
        cnt[tid] = 0;                      // reuse as local rank cursor
    }
    __syncthreads();
    if (i < N_PAIRS) {
        int r = atomicAdd(&cnt[sp], 1);
        d_sorted[base[sp] + r] = i;
    }
}

// ---------------- bf16 split helpers ----------------

// split (f0, f1) -> bf16x2 hi reg (lo half = f0) + bf16x2 residual reg
__device__ __forceinline__ void splitpack(float f0, float f1,
                                          uint32_t& hi, uint32_t& lo) {
    asm("cvt.rn.bf16x2.f32 %0, %2, %1;" : "=r"(hi) : "f"(f0), "f"(f1));
    uint32_t u0 = hi << 16;
    uint32_t u1 = hi & 0xFFFF0000u;
    float r0 = f0 - __uint_as_float(u0);
    float r1 = f1 - __uint_as_float(u1);
    asm("cvt.rn.bf16x2.f32 %0, %2, %1;" : "=r"(lo) : "f"(r0), "f"(r1));
}

// silu via tanh.approx (1 MUFU op): silu(v) = fma(0.5v, tanh(0.5v), 0.5v)
__device__ __forceinline__ float silu(float v) {
    float h = 0.5f * v;
    float t;
    asm("tanh.approx.f32 %0, %1;" : "=f"(t) : "f"(h));
    return fmaf(h, t, h);
}

// ---------------- mma.sync (legacy HMMA, valid on plain sm_103 target) ----------------

__device__ __forceinline__ void mma16816(float* c, const uint32_t* a,
                                         uint32_t b0, uint32_t b1) {
    asm volatile(
        "mma.sync.aligned.m16n8k16.row.col.f32.bf16.bf16.f32 "
        "{%0,%1,%2,%3}, {%4,%5,%6,%7}, {%8,%9}, {%0,%1,%2,%3};"
        : "+f"(c[0]), "+f"(c[1]), "+f"(c[2]), "+f"(c[3])
        : "r"(a[0]), "r"(a[1]), "r"(a[2]), "r"(a[3]), "r"(b0), "r"(b1));
}

// C(m16n8) thread mapping == A(m16n8k16) k-halves: chain layers in registers.
__device__ __forceinline__ void epilogue(float acc[][4],
                                         uint32_t Ah[2][4], uint32_t Al[2][4]) {
#pragma unroll
    for (int j = 0; j < 2; ++j) {
        float s00 = silu(acc[2*j][0]),   s01 = silu(acc[2*j][1]);
        float s02 = silu(acc[2*j][2]),   s03 = silu(acc[2*j][3]);
        float s10 = silu(acc[2*j+1][0]), s11 = silu(acc[2*j+1][1]);
        float s12 = silu(acc[2*j+1][2]), s13 = silu(acc[2*j+1][3]);
        splitpack(s00, s01, Ah[j][0], Al[j][0]);
        splitpack(s02, s03, Ah[j][1], Al[j][1]);
        splitpack(s10, s11, Ah[j][2], Al[j][2]);
        splitpack(s12, s13, Ah[j][3], Al[j][3]);
    }
}

// issue the 3-term split MMA group for one B fragment (packed uint4)
__device__ __forceinline__ void mma3(float* acc, const uint32_t* Ah,
                                     const uint32_t* Al, uint4 w) {
    mma16816(acc, Ah, w.x, w.y);   // hi*Wh
    mma16816(acc, Al, w.x, w.y);   // lo*Wh
    mma16816(acc, Ah, w.z, w.w);   // hi*Wl
}

// ---------------- main MLP kernel (fragment prep fused in) ----------------
// B fragment (mma.m16n8k16, col-major B = W[k][n]):
//   lane: q = lane&3, col = lane>>2; k0 = ktile*16 + 2q; n = ntile*8 + col
//   reg0 = {W[k0][n], W[k0+1][n]}, reg1 = {W[k0+8][n], W[k0+9][n]}
// Packed smem fragment: uint4 {hi.reg0, hi.reg1, lo.reg0, lo.reg1} (1 LDS.128)
// Tile order: L1: 0..3 (ntile, K=16); L2: 4 + n*2 + k; L3: 12 + n*2 + k;
//             L4: 20 + n*2 + k (ntile 0..1, W4 is [32][16]).

__global__ void __launch_bounds__(256, 4)   // 32 warps/SM (<=64 regs)
k_mlp(const float* __restrict__ xg,
      const float* __restrict__ W1, const float* __restrict__ W2,
      const float* __restrict__ W3, const float* __restrict__ W4,
      float* __restrict__ out) {
    const int ls = blockIdx.y;
    const int l = ls >> 2, s = ls & 3;

    __shared__ uint4 wfr[NTILES * 32];   // 12 KB

    // fused fragment prep: each CTA builds its (l,s) fragments into smem
    for (int slot = threadIdx.x; slot < NTILES * 32; slot += 256) {
        const int tile = slot >> 5, lane = slot & 31;
        const int q = lane & 3, col = lane >> 2;
        const float* W;
        int N, nt, kt;
        if (tile < 4)       { W = W1 + ls * 512;  N = 32; nt = tile;           kt = 0; }
        else if (tile < 12) { W = W2 + ls * 1024; N = 32; nt = (tile-4)  >> 1; kt = (tile-4)  & 1; }
        else if (tile < 20) { W = W3 + ls * 1024; N = 32; nt = (tile-12) >> 1; kt = (tile-12) & 1; }
        else                { W = W4 + ls * 512;  N = 16; nt = (tile-20) >> 1; kt = (tile-20) & 1; }
        const int k0 = kt * 16 + q * 2;
        const int n  = nt * 8 + col;
        float e0 = W[(k0 + 0) * N + n], e1 = W[(k0 + 1) * N + n];
        float e2 = W[(k0 + 8) * N + n], e3 = W[(k0 + 9) * N + n];
        uint4 f;
        splitpack(e0, e1, f.x, f.z);
        splitpack(e2, e3, f.y, f.w);
        wfr[slot] = f;
    }

    // bucket offset + count from d_count (local prefix over <=4)
    int beg = 0;
#pragma unroll
    for (int t = 0; t < NSPEC; ++t) if (t < s) beg += d_count[t];
    const int cnt = d_count[s];
    __syncthreads();

    const int lane = threadIdx.x & 31, wid = threadIdx.x >> 5;
    const int q = lane & 3, g = lane >> 2;
    const int ntile = (cnt + 15) >> 4;

    for (int t = blockIdx.x * 8 + wid; t < ntile; t += gridDim.x * 8) {
        int r0 = t * 16 + g;     if (r0 >= cnt) r0 = cnt - 1;
        int r1 = t * 16 + g + 8; if (r1 >= cnt) r1 = cnt - 1;
        const int i0 = d_sorted[beg + r0];
        const int i1 = d_sorted[beg + r1];
        const float* p0 = xg + (size_t)i0 * (LMAX * NM) + l * NM;
        const float* p1 = xg + (size_t)i1 * (LMAX * NM) + l * NM;

        // A fragment: rows {g, g+8}, cols {2q,2q+1} and {2q+8,2q+9}
        float2 v00 = *reinterpret_cast<const float2*>(p0 + 2 * q);
        float2 v01 = *reinterpret_cast<const float2*>(p0 + 2 * q + 8);
        float2 v10 = *reinterpret_cast<const float2*>(p1 + 2 * q);
        float2 v11 = *reinterpret_cast<const float2*>(p1 + 2 * q + 8);

        uint32_t Ah[2][4], Al[2][4];
        splitpack(v00.x, v00.y, Ah[0][0], Al[0][0]);
        splitpack(v10.x, v10.y, Ah[0][1], Al[0][1]);
        splitpack(v01.x, v01.y, Ah[0][2], Al[0][2]);
        splitpack(v11.x, v11.y, Ah[0][3], Al[0][3]);

        float acc[4][4];

        // ---- L1: K=16, tiles 0..3 ----
#pragma unroll
        for (int n = 0; n < 4; ++n) {
#pragma unroll
            for (int e = 0; e < 4; ++e) acc[n][e] = 0.f;
            mma3(acc[n], Ah[0], Al[0], wfr[n * 32 + lane]);
        }
        epilogue(acc, Ah, Al);

        // ---- L2, L3: K=32, tiles 4.. and 12.. ----
#pragma unroll
        for (int base = 4; base <= 12; base += 8) {
#pragma unroll
            for (int n = 0; n < 4; ++n) {
#pragma unroll
                for (int e = 0; e < 4; ++e) acc[n][e] = 0.f;
#pragma unroll
                for (int k = 0; k < 2; ++k)
                    mma3(acc[n], Ah[k], Al[k], wfr[(base + n * 2 + k) * 32 + lane]);
            }
            epilogue(acc, Ah, Al);
        }

        // ---- L4: K=32, N=16, tiles 20..23 ----
#pragma unroll
        for (int n = 0; n < 2; ++n) {
#pragma unroll
            for (int e = 0; e < 4; ++e) acc[n][e] = 0.f;
#pragma unroll
            for (int k = 0; k < 2; ++k)
                mma3(acc[n], Ah[k], Al[k], wfr[(20 + n * 2 + k) * 32 + lane]);
        }

        // ---- write out: C(m16n8) mapping, 2 rows x 2 ntiles x float2 ----
        float* o0 = out + (size_t)i0 * (LMAX * NM) + l * NM;
        float* o1 = out + (size_t)i1 * (LMAX * NM) + l * NM;
        *reinterpret_cast<float2*>(o0 + 2 * q)     = make_float2(acc[0][0], acc[0][1]);
        *reinterpret_cast<float2*>(o0 + 2 * q + 8) = make_float2(acc[1][0], acc[1][1]);
        *reinterpret_cast<float2*>(o1 + 2 * q)     = make_float2(acc[0][2], acc[0][3]);
        *reinterpret_cast<float2*>(o1 + 2 * q + 8) = make_float2(acc[1][2], acc[1][3]);
    }
}

// ---------------- launch ----------------

extern "C" void kernel_launch(void* const* d_in, const int* in_sizes, int n_in,
                              void* d_out, int out_size) {
    const float* x   = (const float*)d_in[0];
    const int*   sp  = (const int*)d_in[1];   // int32 or int64 — detected on device
    const float* W1  = (const float*)d_in[2];
    const float* W2  = (const float*)d_in[3];
    const float* W3  = (const float*)d_in[4];
    const float* W4  = (const float*)d_in[5];
    float*       out = (float*)d_out;

    const int nblk = (N_PAIRS + 255) / 256;

    k_zero<<<1, 32>>>();
    k_hist<<<nblk, 256>>>(sp);
    k_scatter<<<nblk, 256>>>(sp);

    // 36 x 16 = 576 CTAs ~= 4/SM one wave; 8 warps per CTA
    dim3 grid(36, LMAX * NSPEC);
    k_mlp<<<grid, 256>>>(x, W1, W2, W3, W4, out);
}